// round 8
// baseline (speedup 1.0000x reference)
#include <cuda_runtime.h>
#include <cstddef>
#include <cstdint>

#define VOCABN 50000
#define DIMN   300
#define HN     100
#define TN     512
#define BN     256
#define OUTN   3
#define G4     400   // 4*H
#define G4P    448   // padded N (7 tiles of 64)
#define KP0    304   // padded K for layer-0 table GEMM (emb K=300)
#define KP1    112   // padded K for xg GEMMs (h K=100)

// ---------------- scratch (static device globals; no allocation) ----------------
__device__ float g_table[(size_t)VOCABN * G4];
__device__ float g_xg[(size_t)BN * TN * G4];
__device__ float g_h[(size_t)BN * TN * HN];
__device__ float g_hlast[BN * HN];
__device__ int   g_order[BN];
__device__ float g_w0p[(size_t)G4P * KP0];
__device__ float g_w1p[(size_t)G4P * KP1];
__device__ float g_w2p[(size_t)G4P * KP1];

// ---------------- packed f32x2 helpers ----------------
typedef unsigned long long ull;

__device__ __forceinline__ ull pack2(float x, float y) {
    ull r;
    asm("mov.b64 %0, {%1, %2};" : "=l"(r) : "f"(x), "f"(y));
    return r;
}
__device__ __forceinline__ void unpack2(ull v, float& x, float& y) {
    asm("mov.b64 {%0, %1}, %2;" : "=f"(x), "=f"(y) : "l"(v));
}
__device__ __forceinline__ ull fma2(ull a, ull b, ull c) {
    ull d;
    asm("fma.rn.f32x2 %0, %1, %2, %3;" : "=l"(d) : "l"(a), "l"(b), "l"(c));
    return d;
}

// ---------------- tf32 helpers ----------------
__device__ __forceinline__ uint32_t f2tf(float x) {
    uint32_t r;
    asm("cvt.rna.tf32.f32 %0, %1;" : "=r"(r) : "f"(x));
    return r;
}
__device__ __forceinline__ void cvt_hl(float v, uint32_t& h, uint32_t& l) {
    h = f2tf(v);
    float lo = v - __uint_as_float(h);
    l = f2tf(lo);
}
__device__ __forceinline__ void mma_tf32(float (&d)[4], const uint32_t (&a)[4], const uint32_t (&b)[2]) {
    asm volatile(
        "mma.sync.aligned.m16n8k8.row.col.f32.tf32.tf32.f32 "
        "{%0,%1,%2,%3}, {%4,%5,%6,%7}, {%8,%9}, {%0,%1,%2,%3};"
        : "+f"(d[0]), "+f"(d[1]), "+f"(d[2]), "+f"(d[3])
        : "r"(a[0]), "r"(a[1]), "r"(a[2]), "r"(a[3]), "r"(b[0]), "r"(b[1]));
}

// ---------------- length-descending schedule ----------------
__global__ void sort_order(const int* __restrict__ lengths, int* __restrict__ order)
{
    __shared__ int ls[BN];
    int b = threadIdx.x;
    ls[b] = lengths[b];
    __syncthreads();
    int len = ls[b];
    int rank = 0;
#pragma unroll 8
    for (int j = 0; j < BN; j++) {
        int lj = ls[j];
        rank += (lj > len) || (lj == len && j < b);
    }
    order[rank] = b;
}

// ---------------- weight zero-padding: [400,K] -> [448,Kp] ----------------
__global__ void pad_w(const float* __restrict__ src, float* __restrict__ dst,
                      int K, int Kp)
{
    int idx = blockIdx.x * 256 + threadIdx.x;
    int total = G4P * Kp;
    if (idx >= total) return;
    int r = idx / Kp, k = idx % Kp;
    dst[idx] = (r < G4 && k < K) ? src[r * K + k] : 0.f;
}

// ---------------- 3xTF32 tensor-core GEMM (round-5, known good) ----------------
template<int SKIP>
__global__ void __launch_bounds__(256)
gemm_tf32(const float* __restrict__ A, int M, int Ks, int Kreal,
          const float* __restrict__ Bp, int Kp,
          const float* __restrict__ bias1, const float* __restrict__ bias2,
          const int* __restrict__ lengths, float* __restrict__ C)
{
    const int N = G4;
    const int m0 = blockIdx.y * 128;
    const int n0 = blockIdx.x * 64;
    if (SKIP) {
        int b  = m0 / TN;
        int t0 = m0 % TN;
        if (t0 >= lengths[b]) return;
    }

    __shared__ uint32_t As_hi[128 * 20], As_lo[128 * 20];
    __shared__ uint32_t Bs_hi[64 * 20],  Bs_lo[64 * 20];
    __shared__ float bias_s[64];

    const int tid  = threadIdx.x;
    const int wid  = tid >> 5;
    const int lane = tid & 31;
    const int wm   = wid & 3;
    const int wn   = wid >> 2;
    const int gid  = lane >> 2;
    const int tq   = lane & 3;

    if (tid < 64) {
        int n = n0 + tid;
        bias_s[tid] = (n < N) ? bias1[n] + bias2[n] : 0.f;
    }

    int mA[2], kqA[2];
#pragma unroll
    for (int i = 0; i < 2; i++) { int f = i * 256 + tid; mA[i] = f >> 2; kqA[i] = (f & 3) * 4; }
    const int nB = tid >> 2, kqB = (tid & 3) * 4;

    const float* aP[2];
#pragma unroll
    for (int i = 0; i < 2; i++) {
        int mg = m0 + mA[i]; if (mg > M - 1) mg = M - 1;
        aP[i] = A + (size_t)mg * Ks;
    }
    const float* bP = Bp + (size_t)(n0 + nB) * Kp;

    float acc[2][4][4];
#pragma unroll
    for (int i = 0; i < 2; i++)
#pragma unroll
        for (int j = 0; j < 4; j++)
#pragma unroll
            for (int q = 0; q < 4; q++) acc[i][j][q] = 0.f;

    const int kcl = Kreal - 4;
    float4 ra[2], rb;
#pragma unroll
    for (int i = 0; i < 2; i++) {
        int kk = kqA[i]; if (kk > kcl) kk = kcl;
        ra[i] = *reinterpret_cast<const float4*>(aP[i] + kk);
    }
    rb = *reinterpret_cast<const float4*>(bP + kqB);

    for (int k0 = 0; k0 < Kp; k0 += 16) {
#pragma unroll
        for (int i = 0; i < 2; i++) {
            uint32_t h0, l0, h1, l1, h2, l2, h3, l3;
            cvt_hl(ra[i].x, h0, l0); cvt_hl(ra[i].y, h1, l1);
            cvt_hl(ra[i].z, h2, l2); cvt_hl(ra[i].w, h3, l3);
            int off = mA[i] * 20 + kqA[i];
            *reinterpret_cast<uint4*>(&As_hi[off]) = make_uint4(h0, h1, h2, h3);
            *reinterpret_cast<uint4*>(&As_lo[off]) = make_uint4(l0, l1, l2, l3);
        }
        {
            uint32_t h0, l0, h1, l1, h2, l2, h3, l3;
            cvt_hl(rb.x, h0, l0); cvt_hl(rb.y, h1, l1);
            cvt_hl(rb.z, h2, l2); cvt_hl(rb.w, h3, l3);
            int off = nB * 20 + kqB;
            *reinterpret_cast<uint4*>(&Bs_hi[off]) = make_uint4(h0, h1, h2, h3);
            *reinterpret_cast<uint4*>(&Bs_lo[off]) = make_uint4(l0, l1, l2, l3);
        }
        __syncthreads();

        int k0n = k0 + 16;
        if (k0n < Kp) {
#pragma unroll
            for (int i = 0; i < 2; i++) {
                int kk = k0n + kqA[i]; if (kk > kcl) kk = kcl;
                ra[i] = *reinterpret_cast<const float4*>(aP[i] + kk);
            }
            rb = *reinterpret_cast<const float4*>(bP + k0n + kqB);
        }

#pragma unroll
        for (int ks = 0; ks < 2; ks++) {
            const int kb = ks * 8;
            uint32_t ah[2][4], al[2][4];
#pragma unroll
            for (int mf = 0; mf < 2; mf++) {
                int base = (wm * 32 + mf * 16 + gid) * 20 + kb + tq;
                ah[mf][0] = As_hi[base];              al[mf][0] = As_lo[base];
                ah[mf][1] = As_hi[base + 8 * 20];     al[mf][1] = As_lo[base + 8 * 20];
                ah[mf][2] = As_hi[base + 4];          al[mf][2] = As_lo[base + 4];
                ah[mf][3] = As_hi[base + 8 * 20 + 4]; al[mf][3] = As_lo[base + 8 * 20 + 4];
            }
            uint32_t bh[4][2], bl[4][2];
#pragma unroll
            for (int nf = 0; nf < 4; nf++) {
                int base = (wn * 32 + nf * 8 + gid) * 20 + kb + tq;
                bh[nf][0] = Bs_hi[base];     bl[nf][0] = Bs_lo[base];
                bh[nf][1] = Bs_hi[base + 4]; bl[nf][1] = Bs_lo[base + 4];
            }
#pragma unroll
            for (int mf = 0; mf < 2; mf++)
#pragma unroll
                for (int nf = 0; nf < 4; nf++) {
                    mma_tf32(acc[mf][nf], ah[mf], bh[nf]);
                    mma_tf32(acc[mf][nf], ah[mf], bl[nf]);
                    mma_tf32(acc[mf][nf], al[mf], bh[nf]);
                }
        }
        __syncthreads();
    }

#pragma unroll
    for (int mf = 0; mf < 2; mf++) {
#pragma unroll
        for (int nf = 0; nf < 4; nf++) {
            int row0 = m0 + wm * 32 + mf * 16 + gid;
            int cb   = wn * 32 + nf * 8 + 2 * tq;
            int col  = n0 + cb;
            if (col < N) {
                float b0v = bias_s[cb], b1v = bias_s[cb + 1];
                if (row0 < M) {
                    float2 v = make_float2(acc[mf][nf][0] + b0v, acc[mf][nf][1] + b1v);
                    *reinterpret_cast<float2*>(&C[(size_t)row0 * N + col]) = v;
                }
                int row1 = row0 + 8;
                if (row1 < M) {
                    float2 v = make_float2(acc[mf][nf][2] + b0v, acc[mf][nf][3] + b1v);
                    *reinterpret_cast<float2*>(&C[(size_t)row1 * N + col]) = v;
                }
            }
        }
    }
}

// ---------------- LSTM scan (round-5 layout + 4-deep xg prefetch) ----------------
__device__ __forceinline__ float tanh_(float x) { return 2.f / (1.f + __expf(-2.f * x)) - 1.f; }

// thread tid = j*4 + g : hidden unit j (0..99), gate g (0=i,1=f,2=g,3=o)
// Time loop unrolled x4 with 4 named prefetch registers -> each xg LDG has
// ~3 steps to complete before consumption. Overshoot steps (< 4) are masked.
template<int MODE>
__global__ void __launch_bounds__(400, 1)
lstm_scan(const float* __restrict__ xg,
          const int* __restrict__ xtok,
          const int* __restrict__ lengths,
          const int* __restrict__ order,
          const float* __restrict__ w_hh,     // [400,100]
          float* __restrict__ h_out,          // [B,T,100]
          float* __restrict__ hlast)          // [B,100]
{
    const int b   = order[blockIdx.x];
    const int tid = threadIdx.x;
    const int j   = tid >> 2;
    const int g   = tid & 3;
    const int r   = g * 100 + j;

    __shared__ __align__(16) float h_s[2][104];
    __shared__ int idx_s[TN];

    const int len = lengths[b];

    if (MODE == 0) {
        for (int t = tid; t < TN; t += 400) idx_s[t] = xtok[b * TN + t];
    }

    ull w2[50];
    {
        const ull* wrow = reinterpret_cast<const ull*>(w_hh + r * 100);
#pragma unroll
        for (int q = 0; q < 50; q++) w2[q] = wrow[q];
    }

    if (tid < 100) h_s[0][tid] = 0.f;
    float c = 0.f, hk = 0.f;
    __syncthreads();

    const bool is_t = (g == 2);
    const bool gsel = (g & 2) != 0;

    // xg row loader with clamped timestep
    auto xload = [&](int tt) -> float {
        int tl = tt < len ? tt : len - 1;
        if (MODE == 0) return xg[(size_t)idx_s[tl] * G4 + r];
        else           return xg[((size_t)b * TN + tl) * G4 + r];
    };

    float xv0 = xload(0);
    float xv1 = xload(1);
    float xv2 = xload(2);
    float xv3 = xload(3);

#define SCAN_STEP(TT, XV, PN)                                                   \
    {                                                                           \
        const int tt = (TT);                                                    \
        const ulonglong2* h2 = reinterpret_cast<const ulonglong2*>(h_s[tt & 1]);\
        ull acc0 = pack2((XV), 0.f);                                            \
        ull acc1 = 0ULL, acc2v = 0ULL, acc3v = 0ULL;                            \
        _Pragma("unroll")                                                       \
        for (int q = 0; q < 12; q++) {                                          \
            ulonglong2 ha = h2[2 * q];                                          \
            ulonglong2 hb = h2[2 * q + 1];                                      \
            acc0  = fma2(ha.x, w2[4 * q],     acc0);                            \
            acc1  = fma2(ha.y, w2[4 * q + 1], acc1);                            \
            acc2v = fma2(hb.x, w2[4 * q + 2], acc2v);                           \
            acc3v = fma2(hb.y, w2[4 * q + 3], acc3v);                           \
        }                                                                       \
        {                                                                       \
            ulonglong2 ha = h2[24];                                             \
            acc0 = fma2(ha.x, w2[48], acc0);                                    \
            acc1 = fma2(ha.y, w2[49], acc1);                                    \
        }                                                                       \
        float a0, a1, a2, a3, a4, a5, a6, a7;                                   \
        unpack2(acc0, a0, a1);                                                  \
        unpack2(acc1, a2, a3);                                                  \
        unpack2(acc2v, a4, a5);                                                 \
        unpack2(acc3v, a6, a7);                                                 \
        float accv = ((a0 + a1) + (a2 + a3)) + ((a4 + a5) + (a6 + a7));         \
        float z = is_t ? 2.f * accv : accv;                                     \
        float sgm = 1.f / (1.f + __expf(-z));                                   \
        float gate = is_t ? (2.f * sgm - 1.f) : sgm;                            \
        float v1 = __shfl_xor_sync(0xFFFFFFFFu, gate, 1);                       \
        float pa = (g & 1) ? v1 : gate;                                         \
        float pb = (g & 1) ? gate : v1;                                         \
        float qa = __shfl_xor_sync(0xFFFFFFFFu, pa, 2);                         \
        float qb = __shfl_xor_sync(0xFFFFFFFFu, pb, 2);                         \
        float ig = gsel ? qa : pa;                                              \
        float gg = gsel ? pa : qa;                                              \
        float fg = gsel ? qb : pb;                                              \
        float og = gsel ? pb : qb;                                              \
        bool valid = tt < len;                                                  \
        float cn = fg * c + ig * gg;                                            \
        float hn = og * tanh_(cn);                                              \
        if (valid) c = cn;                                                      \
        if (g == 0) {                                                           \
            hk = valid ? hn : hk;                                               \
            h_s[(tt + 1) & 1][j] = hk;                                          \
            if (MODE != 2) {                                                    \
                if (valid) h_out[((size_t)b * TN + tt) * HN + j] = hn;          \
            } else {                                                            \
                if (tt == len - 1) hlast[b * HN + j] = hn;                      \
            }                                                                   \
        }                                                                       \
        (XV) = xload(PN);                                                       \
        __syncthreads();                                                        \
    }

    for (int t0 = 0; t0 < len; t0 += 4) {
        SCAN_STEP(t0 + 0, xv0, t0 + 4);
        SCAN_STEP(t0 + 1, xv1, t0 + 5);
        SCAN_STEP(t0 + 2, xv2, t0 + 6);
        SCAN_STEP(t0 + 3, xv3, t0 + 7);
    }
#undef SCAN_STEP
}

// ---------------- head ----------------
__global__ void head_kernel(const float* __restrict__ hlast,
                            const float* __restrict__ w_fc,
                            const float* __restrict__ b_fc,
                            float* __restrict__ out)
{
    int b = blockIdx.x * blockDim.x + threadIdx.x;
    if (b >= BN) return;
#pragma unroll
    for (int o = 0; o < OUTN; o++) {
        float s = b_fc[o];
#pragma unroll
        for (int k = 0; k < HN; k++)
            s += hlast[b * HN + k] * w_fc[o * HN + k];
        out[b * OUTN + o] = s;
    }
}

// ---------------- launch (single stream, round-5 schedule) ----------------
extern "C" void kernel_launch(void* const* d_in, const int* in_sizes, int n_in,
                              void* d_out, int out_size)
{
    const int*   x      = (const int*)d_in[0];
    const int*   lens   = (const int*)d_in[1];
    const float* emb    = (const float*)d_in[2];
    const float* w_ih0  = (const float*)d_in[3];
    const float* w_hh0  = (const float*)d_in[4];
    const float* b_ih0  = (const float*)d_in[5];
    const float* b_hh0  = (const float*)d_in[6];
    const float* w_ih1  = (const float*)d_in[7];
    const float* w_hh1  = (const float*)d_in[8];
    const float* b_ih1  = (const float*)d_in[9];
    const float* b_hh1  = (const float*)d_in[10];
    const float* w_ih2  = (const float*)d_in[11];
    const float* w_hh2  = (const float*)d_in[12];
    const float* b_ih2  = (const float*)d_in[13];
    const float* b_hh2  = (const float*)d_in[14];
    const float* w_fc   = (const float*)d_in[15];
    const float* b_fc   = (const float*)d_in[16];
    float* out = (float*)d_out;

    void *p_table, *p_xg, *p_h, *p_hlast, *p_order, *p_w0, *p_w1, *p_w2;
    cudaGetSymbolAddress(&p_table, g_table);
    cudaGetSymbolAddress(&p_xg,    g_xg);
    cudaGetSymbolAddress(&p_h,     g_h);
    cudaGetSymbolAddress(&p_hlast, g_hlast);
    cudaGetSymbolAddress(&p_order, g_order);
    cudaGetSymbolAddress(&p_w0,    g_w0p);
    cudaGetSymbolAddress(&p_w1,    g_w1p);
    cudaGetSymbolAddress(&p_w2,    g_w2p);
    float* table = (float*)p_table;
    float* xg    = (float*)p_xg;
    float* h     = (float*)p_h;
    float* hlast = (float*)p_hlast;
    int*   order = (int*)p_order;
    float* w0p   = (float*)p_w0;
    float* w1p   = (float*)p_w1;
    float* w2p   = (float*)p_w2;

    const int M = BN * TN;

    // 0) schedule + weight padding
    sort_order<<<1, BN>>>(lens, order);
    pad_w<<<(G4P * KP0 + 255) / 256, 256>>>(w_ih0, w0p, DIMN, KP0);
    pad_w<<<(G4P * KP1 + 255) / 256, 256>>>(w_ih1, w1p, HN, KP1);
    pad_w<<<(G4P * KP1 + 255) / 256, 256>>>(w_ih2, w2p, HN, KP1);

    // 1) vocab table GEMM: table = emb @ w_ih0^T + b_ih0 + b_hh0
    {
        dim3 grid(7, (VOCABN + 127) / 128);
        gemm_tf32<0><<<grid, 256>>>(emb, VOCABN, DIMN, DIMN, w0p, KP0,
                                    b_ih0, b_hh0, nullptr, table);
    }
    // 2) layer 0 scan (gathers table rows directly)
    lstm_scan<0><<<BN, 400>>>(table, x, lens, order, w_hh0, h, nullptr);

    // 3) layer 1 xg GEMM (+length tile-skip), then scan
    {
        dim3 grid(7, M / 128);
        gemm_tf32<1><<<grid, 256>>>(h, M, HN, HN, w1p, KP1,
                                    b_ih1, b_hh1, lens, xg);
    }
    lstm_scan<1><<<BN, 400>>>(xg, nullptr, lens, order, w_hh1, h, nullptr);

    // 4) layer 2 xg GEMM, then scan (hlast only)
    {
        dim3 grid(7, M / 128);
        gemm_tf32<1><<<grid, 256>>>(h, M, HN, HN, w2p, KP1,
                                    b_ih2, b_hh2, lens, xg);
    }
    lstm_scan<2><<<BN, 400>>>(xg, nullptr, lens, order, w_hh2, nullptr, hlast);

    // 5) head
    head_kernel<<<1, 256>>>(hlast, w_fc, b_fc, out);
}